// round 2
// baseline (speedup 1.0000x reference)
#include <cuda_runtime.h>
#include <math.h>

#define U   1024
#define Bsz 64
#define T   128
#define Dd  256
#define N5  (5*U)        // 5120
#define N3  (3*U)        // 3072
#define KTOT (Dd + 2*U)  // 2304

// ---------------- static device scratch (no allocations allowed) -------------
__device__ float g_W [KTOT * N5];     // packed [kernel; recurrent_kernel; cell_kernel]  ~47MB
__device__ float g_A [Bsz * KTOT];    // per-batch-row [x_t | h | c]
__device__ float g_zp[2 * Bsz * N5];  // split-K partials of z
__device__ float g_O [Bsz * N3];      // [O1 | O2 | O3]
__device__ float g_fp[8 * Bsz * U];   // split-K partials of O@agg
__device__ float g_s [6];             // attention scalars

// ---------------- helpers ----------------------------------------------------
__device__ __forceinline__ float sigf(float x) { return 1.f / (1.f + expf(-x)); }

__device__ __forceinline__ float blk_reduce_max(float v, float* sm) {
    #pragma unroll
    for (int o = 16; o; o >>= 1) v = fmaxf(v, __shfl_xor_sync(0xffffffffu, v, o));
    int w = threadIdx.x >> 5;
    if ((threadIdx.x & 31) == 0) sm[w] = v;
    __syncthreads();
    float r = sm[0];
    #pragma unroll
    for (int i = 1; i < 8; i++) r = fmaxf(r, sm[i]);
    __syncthreads();
    return r;
}

__device__ __forceinline__ float blk_reduce_sum(float v, float* sm) {
    #pragma unroll
    for (int o = 16; o; o >>= 1) v += __shfl_xor_sync(0xffffffffu, v, o);
    int w = threadIdx.x >> 5;
    if ((threadIdx.x & 31) == 0) sm[w] = v;
    __syncthreads();
    float r = sm[0];
    #pragma unroll
    for (int i = 1; i < 8; i++) r += sm[i];
    __syncthreads();
    return r;
}

struct ScanRes { float excl; float total; };

// exclusive prefix across the 256 threads of the block (in tid order) + total
__device__ __forceinline__ ScanRes blk_scan(float s, float* sm) {
    float ws = s;
    #pragma unroll
    for (int o = 1; o < 32; o <<= 1) {
        float t = __shfl_up_sync(0xffffffffu, ws, o);
        if ((threadIdx.x & 31) >= o) ws += t;
    }
    int w = threadIdx.x >> 5;
    if ((threadIdx.x & 31) == 31) sm[w] = ws;
    __syncthreads();
    float warpBase = 0.f, run = 0.f;
    #pragma unroll
    for (int i = 0; i < 8; i++) { float t = sm[i]; if (i == w) warpBase = run; run += t; }
    __syncthreads();
    ScanRes r; r.excl = warpBase + (ws - s); r.total = run; return r;
}

// ---------------- init kernels ----------------------------------------------
__global__ void kinit_pack(const float* __restrict__ k1,
                           const float* __restrict__ k2,
                           const float* __restrict__ k3) {
    const int n1 = Dd * N5 / 4;
    const int n2 = n1 + U * N5 / 4;
    const int nt = KTOT * N5 / 4;
    float4* dst = reinterpret_cast<float4*>(g_W);
    int idx = blockIdx.x * blockDim.x + threadIdx.x;
    int stride = gridDim.x * blockDim.x;
    for (int i = idx; i < nt; i += stride) {
        float4 v;
        if (i < n1)      v = reinterpret_cast<const float4*>(k1)[i];
        else if (i < n2) v = reinterpret_cast<const float4*>(k2)[i - n1];
        else             v = reinterpret_cast<const float4*>(k3)[i - n2];
        dst[i] = v;
    }
}

__global__ void kinit_scalars(const float* a0, const float* b0,
                              const float* a1, const float* b1,
                              const float* a2, const float* b2,
                              const float* a3, const float* b3,
                              const float* a4, const float* b4,
                              const float* a5, const float* b5) {
    __shared__ float sm[8];
    const float* as[6] = {a0, a1, a2, a3, a4, a5};
    const float* bs[6] = {b0, b1, b2, b3, b4, b5};
    for (int p = 0; p < 6; p++) {
        float s = 0.f;
        for (int i = threadIdx.x; i < U; i += 256) s += as[p][i] * bs[p][i];
        float tot = blk_reduce_sum(s, sm);
        if (threadIdx.x == 0) g_s[p] = tot;
        __syncthreads();
    }
}

__global__ void kinit_A(const float* __restrict__ x) {
    int b = blockIdx.x;
    float* Ab = g_A + b * KTOT;
    for (int i = threadIdx.x; i < KTOT; i += 256)
        Ab[i] = (i < Dd) ? x[(b * T + 0) * Dd + i] : 0.f;
}

// ---------------- shared 64-row GEMM (M=64, 64-col tiles, split-K) -----------
// MODE 0: z  = [x_t|h|c](64x2304) @ g_W(2304x5120), split-K 2x1152, +bias on ks0
// MODE 1: fp = O(64x3072) @ agg(3072x1024),          split-K 8x384
template<int MODE>
__global__ void __launch_bounds__(256) gemm64(const float* __restrict__ Bext,
                                              const float* __restrict__ bias) {
    constexpr int LDA  = (MODE == 0) ? KTOT : N3;
    constexpr int LDB  = (MODE == 0) ? N5   : U;
    constexpr int KLEN = (MODE == 0) ? 1152 : 384;

    const float* Aptr = (MODE == 0) ? g_A : g_O;
    const float* Bptr = (MODE == 0) ? g_W : Bext;
    float*       Optr = (MODE == 0) ? g_zp : g_fp;

    const int n0    = blockIdx.x * 64;
    const int ks    = blockIdx.y;
    const int kbase = ks * KLEN;

    __shared__ float As[32][65];
    __shared__ float Bs[32][64];

    const int tid = threadIdx.x;
    const int tx = tid & 15, ty = tid >> 4;
    const int r0 = ty * 4, c0 = tx * 4;

    const int am  = tid >> 2;          // 0..63   (A row)
    const int akb = (tid & 3) * 8;     // 0,8,16,24
    const int bk  = tid >> 3;          // 0..31   (B row in tile)
    const int bn  = (tid & 7) * 8;     // 0..56

    float acc[4][4] = {};

    for (int kc = 0; kc < KLEN; kc += 32) {
        const float* aSrc = Aptr + am * LDA + kbase + kc + akb;
        float4 av0 = *reinterpret_cast<const float4*>(aSrc);
        float4 av1 = *reinterpret_cast<const float4*>(aSrc + 4);
        As[akb + 0][am] = av0.x; As[akb + 1][am] = av0.y;
        As[akb + 2][am] = av0.z; As[akb + 3][am] = av0.w;
        As[akb + 4][am] = av1.x; As[akb + 5][am] = av1.y;
        As[akb + 6][am] = av1.z; As[akb + 7][am] = av1.w;

        const float* bSrc = Bptr + (size_t)(kbase + kc + bk) * LDB + n0 + bn;
        *reinterpret_cast<float4*>(&Bs[bk][bn])     = *reinterpret_cast<const float4*>(bSrc);
        *reinterpret_cast<float4*>(&Bs[bk][bn + 4]) = *reinterpret_cast<const float4*>(bSrc + 4);
        __syncthreads();

        #pragma unroll
        for (int kk = 0; kk < 32; kk++) {
            float4 bq = *reinterpret_cast<const float4*>(&Bs[kk][c0]);
            float a;
            a = As[kk][r0 + 0]; acc[0][0] += a * bq.x; acc[0][1] += a * bq.y; acc[0][2] += a * bq.z; acc[0][3] += a * bq.w;
            a = As[kk][r0 + 1]; acc[1][0] += a * bq.x; acc[1][1] += a * bq.y; acc[1][2] += a * bq.z; acc[1][3] += a * bq.w;
            a = As[kk][r0 + 2]; acc[2][0] += a * bq.x; acc[2][1] += a * bq.y; acc[2][2] += a * bq.z; acc[2][3] += a * bq.w;
            a = As[kk][r0 + 3]; acc[3][0] += a * bq.x; acc[3][1] += a * bq.y; acc[3][2] += a * bq.z; acc[3][3] += a * bq.w;
        }
        __syncthreads();
    }

    #pragma unroll
    for (int i = 0; i < 4; i++) {
        float4 v = make_float4(acc[i][0], acc[i][1], acc[i][2], acc[i][3]);
        if (MODE == 0 && ks == 0) {
            v.x += bias[n0 + c0 + 0]; v.y += bias[n0 + c0 + 1];
            v.z += bias[n0 + c0 + 2]; v.w += bias[n0 + c0 + 3];
        }
        float* orow = Optr + (size_t)ks * (64 * LDB) + (r0 + i) * LDB + n0 + c0;
        *reinterpret_cast<float4*>(orow) = v;
    }
}

// ---------------- per-step gate kernel (one block per batch row) -------------
__global__ void __launch_bounds__(256) kb() {
    __shared__ float sm[16];
    const int b = blockIdx.x, tid = threadIdx.x;
    const float* z0 = g_zp + b * N5;
    const float* z1 = g_zp + Bsz * N5 + b * N5;
    const int i0 = tid * 4;

    float uz[4], dz[4], rz[4];
    {
        float4 p = *reinterpret_cast<const float4*>(z0 + i0);
        float4 q = *reinterpret_cast<const float4*>(z1 + i0);
        uz[0] = p.x + q.x; uz[1] = p.y + q.y; uz[2] = p.z + q.z; uz[3] = p.w + q.w;
        p = *reinterpret_cast<const float4*>(z0 + U + i0);
        q = *reinterpret_cast<const float4*>(z1 + U + i0);
        dz[0] = p.x + q.x; dz[1] = p.y + q.y; dz[2] = p.z + q.z; dz[3] = p.w + q.w;
        p = *reinterpret_cast<const float4*>(z0 + 2 * U + i0);
        q = *reinterpret_cast<const float4*>(z1 + 2 * U + i0);
        rz[0] = p.x + q.x; rz[1] = p.y + q.y; rz[2] = p.z + q.z; rz[3] = p.w + q.w;
    }

    // up = cumsum_l2r(softmax(uz))
    float mx = fmaxf(fmaxf(uz[0], uz[1]), fmaxf(uz[2], uz[3]));
    mx = blk_reduce_max(mx, sm);
    float e[4], ls = 0.f;
    #pragma unroll
    for (int l = 0; l < 4; l++) { e[l] = expf(uz[l] - mx); ls += e[l]; }
    ScanRes s1 = blk_scan(ls, sm);
    float up[4];
    { float P = s1.excl, inv = 1.f / s1.total;
      #pragma unroll
      for (int l = 0; l < 4; l++) { P += e[l]; up[l] = P * inv; } }

    // down = cumsum_r2l(softmax(dz))  == (S - prefix_incl + e)/S
    float mx2 = fmaxf(fmaxf(dz[0], dz[1]), fmaxf(dz[2], dz[3]));
    mx2 = blk_reduce_max(mx2, sm);
    float ed[4]; ls = 0.f;
    #pragma unroll
    for (int l = 0; l < 4; l++) { ed[l] = expf(dz[l] - mx2); ls += ed[l]; }
    ScanRes s2 = blk_scan(ls, sm);
    float dn[4];
    { float P = s2.excl, inv = 1.f / s2.total;
      #pragma unroll
      for (int l = 0; l < 4; l++) { P += ed[l]; dn[l] = (s2.total - P + ed[l]) * inv; } }

    // row dots
    float pdu = 0.f, pru = 0.f, pdr = 0.f;
    #pragma unroll
    for (int l = 0; l < 4; l++) { pdu += dn[l] * up[l]; pru += rz[l] * up[l]; pdr += dn[l] * rz[l]; }
    float du = blk_reduce_sum(pdu, sm);
    float ru = blk_reduce_sum(pru, sm);
    float dr = blk_reduce_sum(pdr, sm);

    const float s_ud = g_s[0], s_ur = g_s[1], s_ru = g_s[2];
    const float s_rd = g_s[3], s_du = g_s[4], s_dr = g_s[5];

    float* Ob = g_O + b * N3;
    float4 o1, o2, o3;
    float t1[4], t2[4], t3[4];
    #pragma unroll
    for (int l = 0; l < 4; l++) {
        t1[l] = sigf(s_ud * up[l] * du) + sigf(s_ur * up[l] * ru);
        t2[l] = sigf(s_ru * rz[l] * ru) + sigf(s_rd * rz[l] * dr);
        t3[l] = sigf(s_du * dn[l] * du) + sigf(s_dr * dn[l] * dr);
    }
    o1 = make_float4(t1[0], t1[1], t1[2], t1[3]);
    o2 = make_float4(t2[0], t2[1], t2[2], t2[3]);
    o3 = make_float4(t3[0], t3[1], t3[2], t3[3]);
    *reinterpret_cast<float4*>(Ob + i0)         = o1;
    *reinterpret_cast<float4*>(Ob + U + i0)     = o2;
    *reinterpret_cast<float4*>(Ob + 2 * U + i0) = o3;
}

// ---------------- per-step update kernel -------------------------------------
__global__ void __launch_bounds__(256) kc2(const float* __restrict__ x,
                                           float* __restrict__ out, int t) {
    const int b = blockIdx.x, tid = threadIdx.x;
    const float* z0 = g_zp + b * N5;
    const float* z1 = g_zp + Bsz * N5 + b * N5;
    float* Ab = g_A + b * KTOT;
    const int j0 = tid * 4;

    #pragma unroll
    for (int l = 0; l < 4; l++) {
        int j = j0 + l;
        float fs = 0.f;
        #pragma unroll
        for (int ks = 0; ks < 8; ks++) fs += g_fp[(ks * Bsz + b) * U + j];
        float f  = sigf(fs);
        float og = z0[3 * U + j] + z1[3 * U + j];
        float ci = tanhf(z0[4 * U + j] + z1[4 * U + j]);
        float co = Ab[Dd + U + j];
        float cn = f * co + (1.f - f) * ci;
        float hn = og * tanhf(cn);
        Ab[Dd + U + j] = cn;   // c
        Ab[Dd + j]     = hn;   // h
        out[((size_t)b * T + t) * U + j] = hn;
    }
    if (t + 1 < T && tid < 64) {
        #pragma unroll
        for (int l = 0; l < 4; l++) {
            int d = tid * 4 + l;
            Ab[d] = x[((size_t)b * T + (t + 1)) * Dd + d];
        }
    }
}

// ---------------- launch ------------------------------------------------------
extern "C" void kernel_launch(void* const* d_in, const int* in_sizes, int n_in,
                              void* d_out, int out_size) {
    const float* x    = (const float*)d_in[0];
    const float* kern = (const float*)d_in[1];
    const float* rker = (const float*)d_in[2];
    const float* cker = (const float*)d_in[3];
    const float* bias = (const float*)d_in[4];
    const float* agg  = (const float*)d_in[5];
    float* out = (float*)d_out;

    kinit_pack<<<2048, 256>>>(kern, rker, cker);
    kinit_scalars<<<1, 256>>>((const float*)d_in[6],  (const float*)d_in[7],
                              (const float*)d_in[8],  (const float*)d_in[9],
                              (const float*)d_in[10], (const float*)d_in[11],
                              (const float*)d_in[12], (const float*)d_in[13],
                              (const float*)d_in[14], (const float*)d_in[15],
                              (const float*)d_in[16], (const float*)d_in[17]);
    kinit_A<<<Bsz, 256>>>(x);

    for (int t = 0; t < T; t++) {
        gemm64<0><<<dim3(N5 / 64, 2), 256>>>(nullptr, bias);   // z partials
        kb<<<Bsz, 256>>>();                                     // gates -> O
        gemm64<1><<<dim3(U / 64, 8), 256>>>(agg, nullptr);      // f partials
        kc2<<<Bsz, 256>>>(x, out, t);                           // state update
    }
}

// round 4
// speedup vs baseline: 2.4703x; 2.4703x over previous
#include <cuda_runtime.h>
#include <cuda_bf16.h>
#include <math.h>
#include <stdint.h>

#define U   1024
#define Bsz 64
#define T   128
#define Dd  256
#define N5  (5*U)        // 5120
#define N3  (3*U)        // 3072
#define KTOT (Dd + 2*U)  // 2304

#define ZSPLIT 4
#define ZKLEN  (KTOT / ZSPLIT)   // 576
#define FSPLIT 16
#define FKLEN  (N3 / FSPLIT)     // 192
#define NTILE  128
#define KCH    32                // K elems per chunk

// SMEM tile geometry: rows padded to 80B (40 bf16) -> conflict-free ldmatrix
#define ROWB   80
#define A_BLK  (64 * ROWB)            // 5120 B per term
#define B_BLK  (128 * ROWB)           // 10240 B per term
#define BUF_BYTES (2*A_BLK + 2*B_BLK) // 30720
#define GSMEM_BYTES (2 * BUF_BYTES)   // 61440

// ---------------- static device scratch --------------------------------------
__device__ __align__(128) __nv_bfloat16 g_Wth[(size_t)N5 * KTOT];  // W^T hi [n][k]
__device__ __align__(128) __nv_bfloat16 g_Wtl[(size_t)N5 * KTOT];  // W^T lo
__device__ __align__(128) __nv_bfloat16 g_AGth[(size_t)U * N3];    // agg^T hi [n][k]
__device__ __align__(128) __nv_bfloat16 g_AGtl[(size_t)U * N3];    // agg^T lo
__device__ __align__(128) __nv_bfloat16 g_Ah[Bsz * KTOT];          // [x|h|c] hi
__device__ __align__(128) __nv_bfloat16 g_Al[Bsz * KTOT];          // [x|h|c] lo
__device__ __align__(128) __nv_bfloat16 g_Oh[Bsz * N3];            // O hi
__device__ __align__(128) __nv_bfloat16 g_Ol[Bsz * N3];            // O lo
__device__ __align__(128) float g_c  [Bsz * U];
__device__ __align__(128) float g_zp [ZSPLIT * Bsz * N5];
__device__ __align__(128) float g_fp [FSPLIT * Bsz * U];
__device__ float g_s[6];

// ---------------- helpers -----------------------------------------------------
__device__ __forceinline__ float sigf(float x) { return 1.f / (1.f + expf(-x)); }

__device__ __forceinline__ uint32_t smem_u32(const void* p) {
    uint32_t a;
    asm("{ .reg .u64 t; cvta.to.shared.u64 t, %1; cvt.u32.u64 %0, t; }" : "=r"(a) : "l"(p));
    return a;
}
__device__ __forceinline__ void bsplit(float v, __nv_bfloat16* hi, __nv_bfloat16* lo) {
    __nv_bfloat16 h = __float2bfloat16(v);
    *hi = h;
    *lo = __float2bfloat16(v - __bfloat162float(h));
}
__device__ __forceinline__ void cpasync16(uint32_t s, const void* g) {
    asm volatile("cp.async.cg.shared.global [%0], [%1], 16;" :: "r"(s), "l"(g) : "memory");
}
__device__ __forceinline__ void cp_commit() { asm volatile("cp.async.commit_group;" ::: "memory"); }
template<int N> __device__ __forceinline__ void cp_wait() {
    asm volatile("cp.async.wait_group %0;" :: "n"(N) : "memory");
}
__device__ __forceinline__ void ldsm4(uint32_t* d, uint32_t addr) {
    asm volatile("ldmatrix.sync.aligned.m8n8.x4.shared.b16 {%0,%1,%2,%3}, [%4];"
                 : "=r"(d[0]), "=r"(d[1]), "=r"(d[2]), "=r"(d[3]) : "r"(addr));
}
__device__ __forceinline__ void mma16816(float* c, const uint32_t* a, const uint32_t* b) {
    asm volatile("mma.sync.aligned.m16n8k16.row.col.f32.bf16.bf16.f32 "
                 "{%0,%1,%2,%3}, {%4,%5,%6,%7}, {%8,%9}, {%0,%1,%2,%3};"
                 : "+f"(c[0]), "+f"(c[1]), "+f"(c[2]), "+f"(c[3])
                 : "r"(a[0]), "r"(a[1]), "r"(a[2]), "r"(a[3]), "r"(b[0]), "r"(b[1]));
}

// ---------------- block reduce helpers ----------------------------------------
__device__ __forceinline__ float blk_reduce_max(float v, float* sm) {
    #pragma unroll
    for (int o = 16; o; o >>= 1) v = fmaxf(v, __shfl_xor_sync(0xffffffffu, v, o));
    int w = threadIdx.x >> 5;
    if ((threadIdx.x & 31) == 0) sm[w] = v;
    __syncthreads();
    float r = sm[0];
    #pragma unroll
    for (int i = 1; i < 8; i++) r = fmaxf(r, sm[i]);
    __syncthreads();
    return r;
}
__device__ __forceinline__ float blk_reduce_sum(float v, float* sm) {
    #pragma unroll
    for (int o = 16; o; o >>= 1) v += __shfl_xor_sync(0xffffffffu, v, o);
    int w = threadIdx.x >> 5;
    if ((threadIdx.x & 31) == 0) sm[w] = v;
    __syncthreads();
    float r = sm[0];
    #pragma unroll
    for (int i = 1; i < 8; i++) r += sm[i];
    __syncthreads();
    return r;
}
struct ScanRes { float excl; float total; };
__device__ __forceinline__ ScanRes blk_scan(float s, float* sm) {
    float ws = s;
    #pragma unroll
    for (int o = 1; o < 32; o <<= 1) {
        float t = __shfl_up_sync(0xffffffffu, ws, o);
        if ((threadIdx.x & 31) >= o) ws += t;
    }
    int w = threadIdx.x >> 5;
    if ((threadIdx.x & 31) == 31) sm[w] = ws;
    __syncthreads();
    float warpBase = 0.f, run = 0.f;
    #pragma unroll
    for (int i = 0; i < 8; i++) { float t = sm[i]; if (i == w) warpBase = run; run += t; }
    __syncthreads();
    ScanRes r; r.excl = warpBase + (ws - s); r.total = run; return r;
}

// ---------------- init: transpose + split weights -----------------------------
__global__ void ktrans_W(const float* __restrict__ k1, const float* __restrict__ k2,
                         const float* __restrict__ k3) {
    __shared__ float tile[32][33];
    int kt = blockIdx.x * 32, nt = blockIdx.y * 32;
    int tx = threadIdx.x, ty = threadIdx.y;   // 32 x 8
    #pragma unroll
    for (int i = 0; i < 32; i += 8) {
        int k = kt + ty + i, n = nt + tx;
        const float* src; int kr;
        if (k < Dd) { src = k1; kr = k; }
        else if (k < Dd + U) { src = k2; kr = k - Dd; }
        else { src = k3; kr = k - Dd - U; }
        tile[ty + i][tx] = src[(size_t)kr * N5 + n];
    }
    __syncthreads();
    #pragma unroll
    for (int i = 0; i < 32; i += 8) {
        int n = nt + ty + i, k = kt + tx;
        float v = tile[tx][ty + i];
        __nv_bfloat16 hi, lo; bsplit(v, &hi, &lo);
        g_Wth[(size_t)n * KTOT + k] = hi;
        g_Wtl[(size_t)n * KTOT + k] = lo;
    }
}
__global__ void ktrans_AG(const float* __restrict__ agg) {
    __shared__ float tile[32][33];
    int kt = blockIdx.x * 32, nt = blockIdx.y * 32;
    int tx = threadIdx.x, ty = threadIdx.y;
    #pragma unroll
    for (int i = 0; i < 32; i += 8)
        tile[ty + i][tx] = agg[(size_t)(kt + ty + i) * U + nt + tx];
    __syncthreads();
    #pragma unroll
    for (int i = 0; i < 32; i += 8) {
        int n = nt + ty + i, k = kt + tx;
        float v = tile[tx][ty + i];
        __nv_bfloat16 hi, lo; bsplit(v, &hi, &lo);
        g_AGth[(size_t)n * N3 + k] = hi;
        g_AGtl[(size_t)n * N3 + k] = lo;
    }
}

__global__ void kinit_scalars(const float* a0, const float* b0, const float* a1, const float* b1,
                              const float* a2, const float* b2, const float* a3, const float* b3,
                              const float* a4, const float* b4, const float* a5, const float* b5) {
    __shared__ float sm[8];
    const float* as[6] = {a0, a1, a2, a3, a4, a5};
    const float* bs[6] = {b0, b1, b2, b3, b4, b5};
    for (int p = 0; p < 6; p++) {
        float s = 0.f;
        for (int i = threadIdx.x; i < U; i += 256) s += as[p][i] * bs[p][i];
        float tot = blk_reduce_sum(s, sm);
        if (threadIdx.x == 0) g_s[p] = tot;
        __syncthreads();
    }
}

__global__ void kinit_A(const float* __restrict__ x) {
    int b = blockIdx.x;
    for (int i = threadIdx.x; i < KTOT; i += 256) {
        float v = (i < Dd) ? x[(size_t)(b * T) * Dd + i] : 0.f;
        __nv_bfloat16 hi, lo; bsplit(v, &hi, &lo);
        g_Ah[b * KTOT + i] = hi;
        g_Al[b * KTOT + i] = lo;
    }
    for (int i = threadIdx.x; i < U; i += 256) g_c[b * U + i] = 0.f;
}

// ---------------- mma.sync GEMM: OUT[ks](64 x NTILE) = A @ W^T ----------------
// 3-term bf16 split: AhWh + AlWh + AhWl, fp32 accum.
// MODE 0: z  (A=g_Ah/g_Al,  W=g_Wth/g_Wtl,  LDK=2304, KLEN=576, +bias on ks0)
// MODE 1: f  (A=g_Oh/g_Ol,  W=g_AGth/g_AGtl, LDK=3072, KLEN=192)
template<int MODE>
__global__ void __launch_bounds__(256) mma_gemm(const float* __restrict__ bias) {
    constexpr int LDK  = (MODE == 0) ? KTOT : N3;
    constexpr int NTOT = (MODE == 0) ? N5 : U;
    constexpr int KLEN = (MODE == 0) ? ZKLEN : FKLEN;
    constexpr int NC   = KLEN / KCH;

    const __nv_bfloat16* Wh = (MODE == 0) ? g_Wth : g_AGth;
    const __nv_bfloat16* Wl = (MODE == 0) ? g_Wtl : g_AGtl;
    const __nv_bfloat16* Ah = (MODE == 0) ? g_Ah : g_Oh;
    const __nv_bfloat16* Al = (MODE == 0) ? g_Al : g_Ol;
    float* OUT = (MODE == 0) ? g_zp : g_fp;

    const int n0    = blockIdx.x * NTILE;
    const int ks    = blockIdx.y;
    const int kbase = ks * KLEN;
    const int tid   = threadIdx.x;
    const int lane  = tid & 31;
    const int w     = tid >> 5;

    extern __shared__ char dyn[];
    const uint32_t smb = smem_u32(dyn);

    // warp tile: m32 x n32
    const int mrow0 = (w & 1) * 32;
    const int nrow0 = (w >> 1) * 32;

    // per-thread ldmatrix row/col bases
    const int rA  = mrow0 + (lane & 15);          // A frag rows
    const int scA = lane >> 4;                    // A frag k-seg offset
    const int rB  = nrow0 + ((lane >> 4) << 3) + (lane & 7);
    const int scB = (lane >> 3) & 1;

    float acc[2][4][4] = {};   // [mi][n8 frag][4]

    // ---- async chunk loader: per chunk 1536 x 16B (A 512, B 1024) ----
    auto load_chunk = [&](int kk, int buf) {
        const uint32_t bb = smb + buf * BUF_BYTES;
        #pragma unroll
        for (int i = 0; i < 6; i++) {
            int seg = tid + i * 256;
            uint32_t dst; const __nv_bfloat16* src;
            if (seg < 512) {
                int term = seg >> 8, idx = seg & 255;
                int r = idx >> 2, s = idx & 3;
                src = (term ? Al : Ah) + (size_t)r * LDK + kk + s * 8;
                dst = bb + term * A_BLK + r * ROWB + s * 16;
            } else {
                int sg = seg - 512;
                int term = sg >> 9, idx = sg & 511;
                int r = idx >> 2, s = idx & 3;
                src = (term ? Wl : Wh) + (size_t)(n0 + r) * LDK + kk + s * 8;
                dst = bb + 2 * A_BLK + term * B_BLK + r * ROWB + s * 16;
            }
            cpasync16(dst, src);
        }
    };

    load_chunk(kbase, 0);
    cp_commit();

    for (int c = 0; c < NC; c++) {
        if (c + 1 < NC) {
            load_chunk(kbase + (c + 1) * KCH, (c + 1) & 1);
            cp_commit();
            cp_wait<1>();
        } else {
            cp_wait<0>();
        }
        __syncthreads();

        const uint32_t bb = smb + (c & 1) * BUF_BYTES;
        #pragma unroll
        for (int s16 = 0; s16 < 2; s16++) {
            const int kd = s16 * 2;   // k seg (16B units) within chunk
            uint32_t ah[2][4], al[2][4], bh[2][4], bl[2][4];
            // A frags: mi tiles at mrow0, mrow0+16
            #pragma unroll
            for (int mi = 0; mi < 2; mi++) {
                uint32_t aH = bb + (rA + mi * 16) * ROWB + (kd + scA) * 16;
                ldsm4(ah[mi], aH);
                ldsm4(al[mi], aH + A_BLK);
            }
            // B frags: two x4 loads cover n32 (4 n8 frags) per term
            #pragma unroll
            for (int nj = 0; nj < 2; nj++) {
                uint32_t bH = bb + 2 * A_BLK + (rB + nj * 16) * ROWB + (kd + scB) * 16;
                ldsm4(bh[nj], bH);
                ldsm4(bl[nj], bH + B_BLK);
            }
            #pragma unroll
            for (int mi = 0; mi < 2; mi++)
                #pragma unroll
                for (int nf = 0; nf < 4; nf++) {
                    const uint32_t* bhf = &bh[nf >> 1][(nf & 1) * 2];
                    const uint32_t* blf = &bl[nf >> 1][(nf & 1) * 2];
                    mma16816(acc[mi][nf], ah[mi], bhf);
                    mma16816(acc[mi][nf], al[mi], bhf);
                    mma16816(acc[mi][nf], ah[mi], blf);
                }
        }
        __syncthreads();
    }

    // ---- epilogue ----
    #pragma unroll
    for (int mi = 0; mi < 2; mi++) {
        #pragma unroll
        for (int nf = 0; nf < 4; nf++) {
            int row = mrow0 + mi * 16 + (lane >> 2);
            int col = n0 + nrow0 + nf * 8 + (lane & 3) * 2;
            float2 v0 = make_float2(acc[mi][nf][0], acc[mi][nf][1]);
            float2 v1 = make_float2(acc[mi][nf][2], acc[mi][nf][3]);
            if (MODE == 0 && ks == 0) {
                v0.x += bias[col]; v0.y += bias[col + 1];
                v1.x += bias[col]; v1.y += bias[col + 1];
            }
            *reinterpret_cast<float2*>(OUT + (size_t)(ks * Bsz + row) * NTOT + col) = v0;
            *reinterpret_cast<float2*>(OUT + (size_t)(ks * Bsz + row + 8) * NTOT + col) = v1;
        }
    }
}

// ---------------- gate kernel -------------------------------------------------
__global__ void __launch_bounds__(256) kb() {
    __shared__ float sm[16];
    const int b = blockIdx.x, tid = threadIdx.x;
    const int i0 = tid * 4;

    float uz[4], dz[4], rz[4];
    {
        #define LOAD4(off, out) {                                                   \
            float4 s0 = *reinterpret_cast<const float4*>(g_zp + (size_t)(0*Bsz+b)*N5 + (off)); \
            float4 s1 = *reinterpret_cast<const float4*>(g_zp + (size_t)(1*Bsz+b)*N5 + (off)); \
            float4 s2 = *reinterpret_cast<const float4*>(g_zp + (size_t)(2*Bsz+b)*N5 + (off)); \
            float4 s3 = *reinterpret_cast<const float4*>(g_zp + (size_t)(3*Bsz+b)*N5 + (off)); \
            out[0] = s0.x + s1.x + s2.x + s3.x; out[1] = s0.y + s1.y + s2.y + s3.y;    \
            out[2] = s0.z + s1.z + s2.z + s3.z; out[3] = s0.w + s1.w + s2.w + s3.w; }
        LOAD4(i0,         uz)
        LOAD4(U + i0,     dz)
        LOAD4(2 * U + i0, rz)
        #undef LOAD4
    }

    float mx = fmaxf(fmaxf(uz[0], uz[1]), fmaxf(uz[2], uz[3]));
    mx = blk_reduce_max(mx, sm);
    float e[4], ls = 0.f;
    #pragma unroll
    for (int l = 0; l < 4; l++) { e[l] = expf(uz[l] - mx); ls += e[l]; }
    ScanRes s1 = blk_scan(ls, sm);
    float up[4];
    { float P = s1.excl, inv = 1.f / s1.total;
      #pragma unroll
      for (int l = 0; l < 4; l++) { P += e[l]; up[l] = P * inv; } }

    float mx2 = fmaxf(fmaxf(dz[0], dz[1]), fmaxf(dz[2], dz[3]));
    mx2 = blk_reduce_max(mx2, sm);
    float ed[4]; ls = 0.f;
    #pragma unroll
    for (int l = 0; l < 4; l++) { ed[l] = expf(dz[l] - mx2); ls += ed[l]; }
    ScanRes s2 = blk_scan(ls, sm);
    float dn[4];
    { float P = s2.excl, inv = 1.f / s2.total;
      #pragma unroll
      for (int l = 0; l < 4; l++) { P += ed[l]; dn[l] = (s2.total - P + ed[l]) * inv; } }

    float pdu = 0.f, pru = 0.f, pdr = 0.f;
    #pragma unroll
    for (int l = 0; l < 4; l++) { pdu += dn[l] * up[l]; pru += rz[l] * up[l]; pdr += dn[l] * rz[l]; }
    float du = blk_reduce_sum(pdu, sm);
    float ru = blk_reduce_sum(pru, sm);
    float dr = blk_reduce_sum(pdr, sm);

    const float s_ud = g_s[0], s_ur = g_s[1], s_ru = g_s[2];
    const float s_rd = g_s[3], s_du = g_s[4], s_dr = g_s[5];

    #pragma unroll
    for (int l = 0; l < 4; l++) {
        float t1 = sigf(s_ud * up[l] * du) + sigf(s_ur * up[l] * ru);
        float t2 = sigf(s_ru * rz[l] * ru) + sigf(s_rd * rz[l] * dr);
        float t3 = sigf(s_du * dn[l] * du) + sigf(s_dr * dn[l] * dr);
        __nv_bfloat16 hi, lo;
        bsplit(t1, &hi, &lo); g_Oh[b * N3 + i0 + l] = hi;         g_Ol[b * N3 + i0 + l] = lo;
        bsplit(t2, &hi, &lo); g_Oh[b * N3 + U + i0 + l] = hi;     g_Ol[b * N3 + U + i0 + l] = lo;
        bsplit(t3, &hi, &lo); g_Oh[b * N3 + 2 * U + i0 + l] = hi; g_Ol[b * N3 + 2 * U + i0 + l] = lo;
    }
}

// ---------------- state-update kernel -----------------------------------------
__global__ void __launch_bounds__(256) kc2(const float* __restrict__ x,
                                           float* __restrict__ out, int t) {
    const int b = blockIdx.x, tid = threadIdx.x;
    const int j0 = tid * 4;

    #pragma unroll
    for (int l = 0; l < 4; l++) {
        int j = j0 + l;
        float fs = 0.f;
        #pragma unroll
        for (int ks = 0; ks < FSPLIT; ks++) fs += g_fp[(size_t)(ks * Bsz + b) * U + j];
        float f = sigf(fs);
        float og = 0.f, zc = 0.f;
        #pragma unroll
        for (int ks = 0; ks < ZSPLIT; ks++) {
            og += g_zp[(size_t)(ks * Bsz + b) * N5 + 3 * U + j];
            zc += g_zp[(size_t)(ks * Bsz + b) * N5 + 4 * U + j];
        }
        float ci = tanhf(zc);
        float co = g_c[b * U + j];
        float cn = f * co + (1.f - f) * ci;
        float hn = og * tanhf(cn);
        g_c[b * U + j] = cn;
        out[((size_t)b * T + t) * U + j] = hn;
        __nv_bfloat16 hi, lo;
        bsplit(hn, &hi, &lo); g_Ah[b * KTOT + Dd + j] = hi;     g_Al[b * KTOT + Dd + j] = lo;
        bsplit(cn, &hi, &lo); g_Ah[b * KTOT + Dd + U + j] = hi; g_Al[b * KTOT + Dd + U + j] = lo;
    }
    if (t + 1 < T && tid < 64) {
        #pragma unroll
        for (int l = 0; l < 4; l++) {
            int d = tid * 4 + l;
            float v = x[((size_t)b * T + (t + 1)) * Dd + d];
            __nv_bfloat16 hi, lo; bsplit(v, &hi, &lo);
            g_Ah[b * KTOT + d] = hi; g_Al[b * KTOT + d] = lo;
        }
    }
}

// ---------------- launch ------------------------------------------------------
extern "C" void kernel_launch(void* const* d_in, const int* in_sizes, int n_in,
                              void* d_out, int out_size) {
    const float* x    = (const float*)d_in[0];
    const float* kern = (const float*)d_in[1];
    const float* rker = (const float*)d_in[2];
    const float* cker = (const float*)d_in[3];
    const float* bias = (const float*)d_in[4];
    const float* agg  = (const float*)d_in[5];
    float* out = (float*)d_out;

    cudaFuncSetAttribute(mma_gemm<0>, cudaFuncAttributeMaxDynamicSharedMemorySize, GSMEM_BYTES);
    cudaFuncSetAttribute(mma_gemm<1>, cudaFuncAttributeMaxDynamicSharedMemorySize, GSMEM_BYTES);

    ktrans_W <<<dim3(KTOT / 32, N5 / 32), dim3(32, 8)>>>(kern, rker, cker);
    ktrans_AG<<<dim3(N3 / 32,  U  / 32), dim3(32, 8)>>>(agg);
    kinit_scalars<<<1, 256>>>((const float*)d_in[6],  (const float*)d_in[7],
                              (const float*)d_in[8],  (const float*)d_in[9],
                              (const float*)d_in[10], (const float*)d_in[11],
                              (const float*)d_in[12], (const float*)d_in[13],
                              (const float*)d_in[14], (const float*)d_in[15],
                              (const float*)d_in[16], (const float*)d_in[17]);
    kinit_A<<<Bsz, 256>>>(x);

    for (int t = 0; t < T; t++) {
        mma_gemm<0><<<dim3(N5 / NTILE, ZSPLIT), 256, GSMEM_BYTES>>>(bias);
        kb<<<Bsz, 256>>>();
        mma_gemm<1><<<dim3(U / NTILE, FSPLIT), 256, GSMEM_BYTES>>>(nullptr);
        kc2<<<Bsz, 256>>>(x, out, t);
    }
}

// round 5
// speedup vs baseline: 3.2099x; 1.2994x over previous
#include <cuda_runtime.h>
#include <cuda_bf16.h>
#include <math.h>
#include <stdint.h>

#define U   1024
#define Bsz 64
#define T   128
#define Dd  256
#define N5  (5*U)        // 5120
#define N3  (3*U)        // 3072
#define KTOT (Dd + 2*U)  // 2304

#define ZSPLIT 3
#define ZKLEN  (KTOT / ZSPLIT)   // 768
#define FSPLIT 16
#define FKLEN  (N3 / FSPLIT)     // 192
#define NTILE  128
#define KCH    64                // K elems per chunk (128 B rows)

// SMEM: rows padded to 144B -> conflict-free ldmatrix (stride 9 x 16B banks)
#define ROWB   144
#define A_BLK  (64 * ROWB)             // 9216 B per term
#define B_BLK  (128 * ROWB)            // 18432 B per term
#define STG_BYTES (2*A_BLK + 2*B_BLK)  // 55296
#define NSTG   3
#define GSMEM_BYTES (NSTG * STG_BYTES) // 165888

// ---------------- static device scratch --------------------------------------
__device__ __align__(128) __nv_bfloat16 g_Wth[(size_t)N5 * KTOT];
__device__ __align__(128) __nv_bfloat16 g_Wtl[(size_t)N5 * KTOT];
__device__ __align__(128) __nv_bfloat16 g_AGth[(size_t)U * N3];
__device__ __align__(128) __nv_bfloat16 g_AGtl[(size_t)U * N3];
__device__ __align__(128) __nv_bfloat16 g_Ah[Bsz * KTOT];
__device__ __align__(128) __nv_bfloat16 g_Al[Bsz * KTOT];
__device__ __align__(128) __nv_bfloat16 g_Oh[Bsz * N3];
__device__ __align__(128) __nv_bfloat16 g_Ol[Bsz * N3];
__device__ __align__(128) float g_c  [Bsz * U];
__device__ __align__(128) float g_zp [ZSPLIT * Bsz * N5];
__device__ __align__(128) float g_fp [FSPLIT * Bsz * U];
__device__ float g_s[6];

// ---------------- helpers -----------------------------------------------------
__device__ __forceinline__ float sigf(float x) { return 1.f / (1.f + expf(-x)); }

__device__ __forceinline__ uint32_t smem_u32(const void* p) {
    uint32_t a;
    asm("{ .reg .u64 t; cvta.to.shared.u64 t, %1; cvt.u32.u64 %0, t; }" : "=r"(a) : "l"(p));
    return a;
}
__device__ __forceinline__ void bsplit(float v, __nv_bfloat16* hi, __nv_bfloat16* lo) {
    __nv_bfloat16 h = __float2bfloat16(v);
    *hi = h;
    *lo = __float2bfloat16(v - __bfloat162float(h));
}
__device__ __forceinline__ void cpasync16(uint32_t s, const void* g) {
    asm volatile("cp.async.cg.shared.global [%0], [%1], 16;" :: "r"(s), "l"(g) : "memory");
}
__device__ __forceinline__ void cp_commit() { asm volatile("cp.async.commit_group;" ::: "memory"); }
template<int N> __device__ __forceinline__ void cp_wait() {
    asm volatile("cp.async.wait_group %0;" :: "n"(N) : "memory");
}
__device__ __forceinline__ void ldsm4(uint32_t* d, uint32_t addr) {
    asm volatile("ldmatrix.sync.aligned.m8n8.x4.shared.b16 {%0,%1,%2,%3}, [%4];"
                 : "=r"(d[0]), "=r"(d[1]), "=r"(d[2]), "=r"(d[3]) : "r"(addr));
}
__device__ __forceinline__ void mma16816(float* c, const uint32_t* a, const uint32_t* b) {
    asm volatile("mma.sync.aligned.m16n8k16.row.col.f32.bf16.bf16.f32 "
                 "{%0,%1,%2,%3}, {%4,%5,%6,%7}, {%8,%9}, {%0,%1,%2,%3};"
                 : "+f"(c[0]), "+f"(c[1]), "+f"(c[2]), "+f"(c[3])
                 : "r"(a[0]), "r"(a[1]), "r"(a[2]), "r"(a[3]), "r"(b[0]), "r"(b[1]));
}

// ---------------- block reduce helpers ----------------------------------------
__device__ __forceinline__ float blk_reduce_max(float v, float* sm) {
    #pragma unroll
    for (int o = 16; o; o >>= 1) v = fmaxf(v, __shfl_xor_sync(0xffffffffu, v, o));
    int w = threadIdx.x >> 5;
    if ((threadIdx.x & 31) == 0) sm[w] = v;
    __syncthreads();
    float r = sm[0];
    #pragma unroll
    for (int i = 1; i < 8; i++) r = fmaxf(r, sm[i]);
    __syncthreads();
    return r;
}
__device__ __forceinline__ float blk_reduce_sum(float v, float* sm) {
    #pragma unroll
    for (int o = 16; o; o >>= 1) v += __shfl_xor_sync(0xffffffffu, v, o);
    int w = threadIdx.x >> 5;
    if ((threadIdx.x & 31) == 0) sm[w] = v;
    __syncthreads();
    float r = sm[0];
    #pragma unroll
    for (int i = 1; i < 8; i++) r += sm[i];
    __syncthreads();
    return r;
}
struct ScanRes { float excl; float total; };
__device__ __forceinline__ ScanRes blk_scan(float s, float* sm) {
    float ws = s;
    #pragma unroll
    for (int o = 1; o < 32; o <<= 1) {
        float t = __shfl_up_sync(0xffffffffu, ws, o);
        if ((threadIdx.x & 31) >= o) ws += t;
    }
    int w = threadIdx.x >> 5;
    if ((threadIdx.x & 31) == 31) sm[w] = ws;
    __syncthreads();
    float warpBase = 0.f, run = 0.f;
    #pragma unroll
    for (int i = 0; i < 8; i++) { float t = sm[i]; if (i == w) warpBase = run; run += t; }
    __syncthreads();
    ScanRes r; r.excl = warpBase + (ws - s); r.total = run; return r;
}

// ---------------- init: transpose + split weights -----------------------------
__global__ void ktrans_W(const float* __restrict__ k1, const float* __restrict__ k2,
                         const float* __restrict__ k3) {
    __shared__ float tile[32][33];
    int kt = blockIdx.x * 32, nt = blockIdx.y * 32;
    int tx = threadIdx.x, ty = threadIdx.y;
    #pragma unroll
    for (int i = 0; i < 32; i += 8) {
        int k = kt + ty + i, n = nt + tx;
        const float* src; int kr;
        if (k < Dd) { src = k1; kr = k; }
        else if (k < Dd + U) { src = k2; kr = k - Dd; }
        else { src = k3; kr = k - Dd - U; }
        tile[ty + i][tx] = src[(size_t)kr * N5 + n];
    }
    __syncthreads();
    #pragma unroll
    for (int i = 0; i < 32; i += 8) {
        int n = nt + ty + i, k = kt + tx;
        float v = tile[tx][ty + i];
        __nv_bfloat16 hi, lo; bsplit(v, &hi, &lo);
        g_Wth[(size_t)n * KTOT + k] = hi;
        g_Wtl[(size_t)n * KTOT + k] = lo;
    }
}
__global__ void ktrans_AG(const float* __restrict__ agg) {
    __shared__ float tile[32][33];
    int kt = blockIdx.x * 32, nt = blockIdx.y * 32;
    int tx = threadIdx.x, ty = threadIdx.y;
    #pragma unroll
    for (int i = 0; i < 32; i += 8)
        tile[ty + i][tx] = agg[(size_t)(kt + ty + i) * U + nt + tx];
    __syncthreads();
    #pragma unroll
    for (int i = 0; i < 32; i += 8) {
        int n = nt + ty + i, k = kt + tx;
        float v = tile[tx][ty + i];
        __nv_bfloat16 hi, lo; bsplit(v, &hi, &lo);
        g_AGth[(size_t)n * N3 + k] = hi;
        g_AGtl[(size_t)n * N3 + k] = lo;
    }
}

__global__ void kinit_scalars(const float* a0, const float* b0, const float* a1, const float* b1,
                              const float* a2, const float* b2, const float* a3, const float* b3,
                              const float* a4, const float* b4, const float* a5, const float* b5) {
    __shared__ float sm[8];
    const float* as[6] = {a0, a1, a2, a3, a4, a5};
    const float* bs[6] = {b0, b1, b2, b3, b4, b5};
    for (int p = 0; p < 6; p++) {
        float s = 0.f;
        for (int i = threadIdx.x; i < U; i += 256) s += as[p][i] * bs[p][i];
        float tot = blk_reduce_sum(s, sm);
        if (threadIdx.x == 0) g_s[p] = tot;
        __syncthreads();
    }
}

__global__ void kinit_A(const float* __restrict__ x) {
    int b = blockIdx.x;
    for (int i = threadIdx.x; i < KTOT; i += 256) {
        float v = (i < Dd) ? x[(size_t)(b * T) * Dd + i] : 0.f;
        __nv_bfloat16 hi, lo; bsplit(v, &hi, &lo);
        g_Ah[b * KTOT + i] = hi;
        g_Al[b * KTOT + i] = lo;
    }
    for (int i = threadIdx.x; i < U; i += 256) g_c[b * U + i] = 0.f;
}

// ---------------- mma.sync GEMM ------------------------------------------------
// OUT[ks](64 x NTILE) = A @ W^T ; 3-term bf16 split; 3-stage cp.async pipeline.
// MODE 0: z (LDK=2304, KLEN=768, +bias on ks0) | MODE 1: f (LDK=3072, KLEN=192)
template<int MODE>
__global__ void __launch_bounds__(256) mma_gemm(const float* __restrict__ bias) {
    constexpr int LDK  = (MODE == 0) ? KTOT : N3;
    constexpr int NTOT = (MODE == 0) ? N5 : U;
    constexpr int KLEN = (MODE == 0) ? ZKLEN : FKLEN;
    constexpr int NC   = KLEN / KCH;
    constexpr int NSPL = (MODE == 0) ? ZSPLIT : FSPLIT;
    (void)NSPL;

    const __nv_bfloat16* Wh = (MODE == 0) ? g_Wth : g_AGth;
    const __nv_bfloat16* Wl = (MODE == 0) ? g_Wtl : g_AGtl;
    const __nv_bfloat16* Ah = (MODE == 0) ? g_Ah : g_Oh;
    const __nv_bfloat16* Al = (MODE == 0) ? g_Al : g_Ol;
    float* OUT = (MODE == 0) ? g_zp : g_fp;

    const int n0    = blockIdx.x * NTILE;
    const int ks    = blockIdx.y;
    const int kbase = ks * KLEN;
    const int tid   = threadIdx.x;
    const int lane  = tid & 31;
    const int w     = tid >> 5;

    extern __shared__ char dyn[];
    const uint32_t smb = smem_u32(dyn);

    // ---- precompute per-thread load descriptors (12 segs of 16B per chunk) ----
    const __nv_bfloat16* srcB[12];
    uint32_t dstO[12];
    #pragma unroll
    for (int i = 0; i < 12; i++) {
        int seg = tid + i * 256;
        if (seg < 1024) {
            int term = seg >> 9, idx = seg & 511;
            int r = idx >> 3, s = idx & 7;
            srcB[i] = (term ? Al : Ah) + (size_t)r * LDK + s * 8;
            dstO[i] = term * A_BLK + r * ROWB + s * 16;
        } else {
            int sg = seg - 1024;
            int term = sg >> 10, idx = sg & 1023;
            int r = idx >> 3, s = idx & 7;
            srcB[i] = (term ? Wl : Wh) + (size_t)(n0 + r) * LDK + s * 8;
            dstO[i] = 2 * A_BLK + term * B_BLK + r * ROWB + s * 16;
        }
    }
    auto load_chunk = [&](int kk, int stg) {
        const uint32_t bb = smb + stg * STG_BYTES;
        #pragma unroll
        for (int i = 0; i < 12; i++)
            cpasync16(bb + dstO[i], srcB[i] + kk);
        cp_commit();
    };

    // warp tile m32 x n32 (2x4 warp grid)
    const int mrow0 = (w & 1) * 32;
    const int nrow0 = (w >> 1) * 32;
    const int rA  = mrow0 + (lane & 15);
    const int scA = lane >> 4;
    const int rB  = nrow0 + ((lane >> 4) << 3) + (lane & 7);
    const int scB = (lane >> 3) & 1;

    float acc[2][4][4] = {};

    // prologue: prefetch chunks 0,1
    load_chunk(kbase, 0);
    if (NC > 1) load_chunk(kbase + KCH, 1);

    for (int c = 0; c < NC; c++) {
        if (c + 1 < NC) cp_wait<1>(); else cp_wait<0>();
        __syncthreads();                       // chunk c arrived; all warps done with c-1
        if (c + 2 < NC) load_chunk(kbase + (c + 2) * KCH, (c + 2) % NSTG);

        const uint32_t bb = smb + (c % NSTG) * STG_BYTES;
        #pragma unroll
        for (int s16 = 0; s16 < 4; s16++) {
            const int kd = s16 * 2;            // 16B units within the 128B row
            uint32_t ah[2][4], al[2][4], bh[2][4], bl[2][4];
            #pragma unroll
            for (int mi = 0; mi < 2; mi++) {
                uint32_t aH = bb + (rA + mi * 16) * ROWB + (kd + scA) * 16;
                ldsm4(ah[mi], aH);
                ldsm4(al[mi], aH + A_BLK);
            }
            #pragma unroll
            for (int nj = 0; nj < 2; nj++) {
                uint32_t bH = bb + 2 * A_BLK + (rB + nj * 16) * ROWB + (kd + scB) * 16;
                ldsm4(bh[nj], bH);
                ldsm4(bl[nj], bH + B_BLK);
            }
            #pragma unroll
            for (int mi = 0; mi < 2; mi++)
                #pragma unroll
                for (int nf = 0; nf < 4; nf++) {
                    const uint32_t* bhf = &bh[nf >> 1][(nf & 1) * 2];
                    const uint32_t* blf = &bl[nf >> 1][(nf & 1) * 2];
                    mma16816(acc[mi][nf], ah[mi], bhf);
                    mma16816(acc[mi][nf], al[mi], bhf);
                    mma16816(acc[mi][nf], ah[mi], blf);
                }
        }
    }

    // epilogue
    #pragma unroll
    for (int mi = 0; mi < 2; mi++) {
        #pragma unroll
        for (int nf = 0; nf < 4; nf++) {
            int row = mrow0 + mi * 16 + (lane >> 2);
            int col = n0 + nrow0 + nf * 8 + (lane & 3) * 2;
            float2 v0 = make_float2(acc[mi][nf][0], acc[mi][nf][1]);
            float2 v1 = make_float2(acc[mi][nf][2], acc[mi][nf][3]);
            if (MODE == 0 && ks == 0) {
                v0.x += bias[col]; v0.y += bias[col + 1];
                v1.x += bias[col]; v1.y += bias[col + 1];
            }
            *reinterpret_cast<float2*>(OUT + (size_t)(ks * Bsz + row) * NTOT + col) = v0;
            *reinterpret_cast<float2*>(OUT + (size_t)(ks * Bsz + row + 8) * NTOT + col) = v1;
        }
    }
}

// ---------------- gate kernel --------------------------------------------------
__global__ void __launch_bounds__(256) kb() {
    __shared__ float sm[16];
    const int b = blockIdx.x, tid = threadIdx.x;
    const int i0 = tid * 4;

    float uz[4], dz[4], rz[4];
    {
        #define LOAD3(off, out) {                                                   \
            float4 s0 = *reinterpret_cast<const float4*>(g_zp + (size_t)(0*Bsz+b)*N5 + (off)); \
            float4 s1 = *reinterpret_cast<const float4*>(g_zp + (size_t)(1*Bsz+b)*N5 + (off)); \
            float4 s2 = *reinterpret_cast<const float4*>(g_zp + (size_t)(2*Bsz+b)*N5 + (off)); \
            out[0] = s0.x + s1.x + s2.x; out[1] = s0.y + s1.y + s2.y;                  \
            out[2] = s0.z + s1.z + s2.z; out[3] = s0.w + s1.w + s2.w; }
        LOAD3(i0,         uz)
        LOAD3(U + i0,     dz)
        LOAD3(2 * U + i0, rz)
        #undef LOAD3
    }

    float mx = fmaxf(fmaxf(uz[0], uz[1]), fmaxf(uz[2], uz[3]));
    mx = blk_reduce_max(mx, sm);
    float e[4], ls = 0.f;
    #pragma unroll
    for (int l = 0; l < 4; l++) { e[l] = expf(uz[l] - mx); ls += e[l]; }
    ScanRes s1 = blk_scan(ls, sm);
    float up[4];
    { float P = s1.excl, inv = 1.f / s1.total;
      #pragma unroll
      for (int l = 0; l < 4; l++) { P += e[l]; up[l] = P * inv; } }

    float mx2 = fmaxf(fmaxf(dz[0], dz[1]), fmaxf(dz[2], dz[3]));
    mx2 = blk_reduce_max(mx2, sm);
    float ed[4]; ls = 0.f;
    #pragma unroll
    for (int l = 0; l < 4; l++) { ed[l] = expf(dz[l] - mx2); ls += ed[l]; }
    ScanRes s2 = blk_scan(ls, sm);
    float dn[4];
    { float P = s2.excl, inv = 1.f / s2.total;
      #pragma unroll
      for (int l = 0; l < 4; l++) { P += ed[l]; dn[l] = (s2.total - P + ed[l]) * inv; } }

    float pdu = 0.f, pru = 0.f, pdr = 0.f;
    #pragma unroll
    for (int l = 0; l < 4; l++) { pdu += dn[l] * up[l]; pru += rz[l] * up[l]; pdr += dn[l] * rz[l]; }
    float du = blk_reduce_sum(pdu, sm);
    float ru = blk_reduce_sum(pru, sm);
    float dr = blk_reduce_sum(pdr, sm);

    const float s_ud = g_s[0], s_ur = g_s[1], s_ru = g_s[2];
    const float s_rd = g_s[3], s_du = g_s[4], s_dr = g_s[5];

    #pragma unroll
    for (int l = 0; l < 4; l++) {
        float t1 = sigf(s_ud * up[l] * du) + sigf(s_ur * up[l] * ru);
        float t2 = sigf(s_ru * rz[l] * ru) + sigf(s_rd * rz[l] * dr);
        float t3 = sigf(s_du * dn[l] * du) + sigf(s_dr * dn[l] * dr);
        __nv_bfloat16 hi, lo;
        bsplit(t1, &hi, &lo); g_Oh[b * N3 + i0 + l] = hi;         g_Ol[b * N3 + i0 + l] = lo;
        bsplit(t2, &hi, &lo); g_Oh[b * N3 + U + i0 + l] = hi;     g_Ol[b * N3 + U + i0 + l] = lo;
        bsplit(t3, &hi, &lo); g_Oh[b * N3 + 2 * U + i0 + l] = hi; g_Ol[b * N3 + 2 * U + i0 + l] = lo;
    }
}

// ---------------- state-update kernel ------------------------------------------
__global__ void __launch_bounds__(256) kc2(const float* __restrict__ x,
                                           float* __restrict__ out, int t) {
    const int b = blockIdx.x, tid = threadIdx.x;
    const int j0 = tid * 4;

    #pragma unroll
    for (int l = 0; l < 4; l++) {
        int j = j0 + l;
        float fs = 0.f;
        #pragma unroll
        for (int ks = 0; ks < FSPLIT; ks++) fs += g_fp[(size_t)(ks * Bsz + b) * U + j];
        float f = sigf(fs);
        float og = 0.f, zc = 0.f;
        #pragma unroll
        for (int ks = 0; ks < ZSPLIT; ks++) {
            og += g_zp[(size_t)(ks * Bsz + b) * N5 + 3 * U + j];
            zc += g_zp[(size_t)(ks * Bsz + b) * N5 + 4 * U + j];
        }
        float ci = tanhf(zc);
        float co = g_c[b * U + j];
        float cn = f * co + (1.f - f) * ci;
        float hn = og * tanhf(cn);
        g_c[b * U + j] = cn;
        out[((size_t)b * T + t) * U + j] = hn;
        __nv_bfloat16 hi, lo;
        bsplit(hn, &hi, &lo); g_Ah[b * KTOT + Dd + j] = hi;     g_Al[b * KTOT + Dd + j] = lo;
        bsplit(cn, &hi, &lo); g_Ah[b * KTOT + Dd + U + j] = hi; g_Al[b * KTOT + Dd + U + j] = lo;
    }
    if (t + 1 < T && tid < 64) {
        #pragma unroll
        for (int l = 0; l < 4; l++) {
            int d = tid * 4 + l;
            float v = x[((size_t)b * T + (t + 1)) * Dd + d];
            __nv_bfloat16 hi, lo; bsplit(v, &hi, &lo);
            g_Ah[b * KTOT + d] = hi; g_Al[b * KTOT + d] = lo;
        }
    }
}

// ---------------- launch --------------------------------------------------------
extern "C" void kernel_launch(void* const* d_in, const int* in_sizes, int n_in,
                              void* d_out, int out_size) {
    const float* x    = (const float*)d_in[0];
    const float* kern = (const float*)d_in[1];
    const float* rker = (const float*)d_in[2];
    const float* cker = (const float*)d_in[3];
    const float* bias = (const float*)d_in[4];
    const float* agg  = (const float*)d_in[5];
    float* out = (float*)d_out;

    cudaFuncSetAttribute(mma_gemm<0>, cudaFuncAttributeMaxDynamicSharedMemorySize, GSMEM_BYTES);
    cudaFuncSetAttribute(mma_gemm<1>, cudaFuncAttributeMaxDynamicSharedMemorySize, GSMEM_BYTES);

    ktrans_W <<<dim3(KTOT / 32, N5 / 32), dim3(32, 8)>>>(kern, rker, cker);
    ktrans_AG<<<dim3(N3 / 32,  U  / 32), dim3(32, 8)>>>(agg);
    kinit_scalars<<<1, 256>>>((const float*)d_in[6],  (const float*)d_in[7],
                              (const float*)d_in[8],  (const float*)d_in[9],
                              (const float*)d_in[10], (const float*)d_in[11],
                              (const float*)d_in[12], (const float*)d_in[13],
                              (const float*)d_in[14], (const float*)d_in[15],
                              (const float*)d_in[16], (const float*)d_in[17]);
    kinit_A<<<Bsz, 256>>>(x);

    for (int t = 0; t < T; t++) {
        mma_gemm<0><<<dim3(N5 / NTILE, ZSPLIT), 256, GSMEM_BYTES>>>(bias);
        kb<<<Bsz, 256>>>();
        mma_gemm<1><<<dim3(U / NTILE, FSPLIT), 256, GSMEM_BYTES>>>(nullptr);
        kc2<<<Bsz, 256>>>(x, out, t);
    }
}

// round 6
// speedup vs baseline: 4.3353x; 1.3506x over previous
#include <cuda_runtime.h>
#include <cuda_fp16.h>
#include <math.h>
#include <stdint.h>

#define U   1024
#define Bsz 64
#define T   128
#define Dd  256
#define N5  (5*U)        // 5120
#define N3  (3*U)        // 3072
#define KTOT (Dd + 2*U)  // 2304

#define ZSPLIT 3
#define ZKLEN  (KTOT / ZSPLIT)   // 768
#define FSPLIT 8
#define FKLEN  (N3 / FSPLIT)     // 384
#define NTILE  128
#define KCH    64                // K elems per chunk (128 B rows fp16)

// SMEM: rows padded to 144B -> conflict-free ldmatrix
#define ROWB   144
#define A_BLK  (64 * ROWB)             // 9216
#define B_BLK  (128 * ROWB)            // 18432
#define STG_BYTES (A_BLK + B_BLK)      // 27648
#define NSTG   4
#define GSMEM_BYTES (NSTG * STG_BYTES) // 110592

// ---------------- static device scratch --------------------------------------
__device__ __align__(128) __half g_Wt [(size_t)N5 * KTOT];  // W^T fp16 [n][k]
__device__ __align__(128) __half g_AGt[(size_t)U * N3];     // agg^T fp16 [n][k]
__device__ __align__(128) __half g_A16[Bsz * KTOT];         // [x|h|c] fp16
__device__ __align__(128) __half g_O16[Bsz * N3];           // O fp16
__device__ __align__(128) float g_c  [Bsz * U];
__device__ __align__(128) float g_zp [ZSPLIT * Bsz * N5];
__device__ __align__(128) float g_fp [FSPLIT * Bsz * U];
__device__ float g_s[6];

// ---------------- helpers -----------------------------------------------------
__device__ __forceinline__ float sigf(float x) { return 1.f / (1.f + expf(-x)); }

__device__ __forceinline__ uint32_t smem_u32(const void* p) {
    uint32_t a;
    asm("{ .reg .u64 t; cvta.to.shared.u64 t, %1; cvt.u32.u64 %0, t; }" : "=r"(a) : "l"(p));
    return a;
}
__device__ __forceinline__ void cpasync16(uint32_t s, const void* g) {
    asm volatile("cp.async.cg.shared.global [%0], [%1], 16;" :: "r"(s), "l"(g) : "memory");
}
__device__ __forceinline__ void cp_commit() { asm volatile("cp.async.commit_group;" ::: "memory"); }
template<int N> __device__ __forceinline__ void cp_wait() {
    asm volatile("cp.async.wait_group %0;" :: "n"(N) : "memory");
}
__device__ __forceinline__ void ldsm4(uint32_t* d, uint32_t addr) {
    asm volatile("ldmatrix.sync.aligned.m8n8.x4.shared.b16 {%0,%1,%2,%3}, [%4];"
                 : "=r"(d[0]), "=r"(d[1]), "=r"(d[2]), "=r"(d[3]) : "r"(addr));
}
__device__ __forceinline__ void mma16816(float* c, const uint32_t* a, const uint32_t* b) {
    asm volatile("mma.sync.aligned.m16n8k16.row.col.f32.f16.f16.f32 "
                 "{%0,%1,%2,%3}, {%4,%5,%6,%7}, {%8,%9}, {%0,%1,%2,%3};"
                 : "+f"(c[0]), "+f"(c[1]), "+f"(c[2]), "+f"(c[3])
                 : "r"(a[0]), "r"(a[1]), "r"(a[2]), "r"(a[3]), "r"(b[0]), "r"(b[1]));
}

// ---------------- block reduce helpers ----------------------------------------
__device__ __forceinline__ float blk_reduce_max(float v, float* sm) {
    #pragma unroll
    for (int o = 16; o; o >>= 1) v = fmaxf(v, __shfl_xor_sync(0xffffffffu, v, o));
    int w = threadIdx.x >> 5;
    if ((threadIdx.x & 31) == 0) sm[w] = v;
    __syncthreads();
    float r = sm[0];
    #pragma unroll
    for (int i = 1; i < 8; i++) r = fmaxf(r, sm[i]);
    __syncthreads();
    return r;
}
__device__ __forceinline__ float blk_reduce_sum(float v, float* sm) {
    #pragma unroll
    for (int o = 16; o; o >>= 1) v += __shfl_xor_sync(0xffffffffu, v, o);
    int w = threadIdx.x >> 5;
    if ((threadIdx.x & 31) == 0) sm[w] = v;
    __syncthreads();
    float r = sm[0];
    #pragma unroll
    for (int i = 1; i < 8; i++) r += sm[i];
    __syncthreads();
    return r;
}
struct ScanRes { float excl; float total; };
__device__ __forceinline__ ScanRes blk_scan(float s, float* sm) {
    float ws = s;
    #pragma unroll
    for (int o = 1; o < 32; o <<= 1) {
        float t = __shfl_up_sync(0xffffffffu, ws, o);
        if ((threadIdx.x & 31) >= o) ws += t;
    }
    int w = threadIdx.x >> 5;
    if ((threadIdx.x & 31) == 31) sm[w] = ws;
    __syncthreads();
    float warpBase = 0.f, run = 0.f;
    #pragma unroll
    for (int i = 0; i < 8; i++) { float t = sm[i]; if (i == w) warpBase = run; run += t; }
    __syncthreads();
    ScanRes r; r.excl = warpBase + (ws - s); r.total = run; return r;
}

// ---------------- init: transpose weights to fp16 ------------------------------
__global__ void ktrans_W(const float* __restrict__ k1, const float* __restrict__ k2,
                         const float* __restrict__ k3) {
    __shared__ float tile[32][33];
    int kt = blockIdx.x * 32, nt = blockIdx.y * 32;
    int tx = threadIdx.x, ty = threadIdx.y;
    #pragma unroll
    for (int i = 0; i < 32; i += 8) {
        int k = kt + ty + i, n = nt + tx;
        const float* src; int kr;
        if (k < Dd) { src = k1; kr = k; }
        else if (k < Dd + U) { src = k2; kr = k - Dd; }
        else { src = k3; kr = k - Dd - U; }
        tile[ty + i][tx] = src[(size_t)kr * N5 + n];
    }
    __syncthreads();
    #pragma unroll
    for (int i = 0; i < 32; i += 8) {
        int n = nt + ty + i, k = kt + tx;
        g_Wt[(size_t)n * KTOT + k] = __float2half(tile[tx][ty + i]);
    }
}
__global__ void ktrans_AG(const float* __restrict__ agg) {
    __shared__ float tile[32][33];
    int kt = blockIdx.x * 32, nt = blockIdx.y * 32;
    int tx = threadIdx.x, ty = threadIdx.y;
    #pragma unroll
    for (int i = 0; i < 32; i += 8)
        tile[ty + i][tx] = agg[(size_t)(kt + ty + i) * U + nt + tx];
    __syncthreads();
    #pragma unroll
    for (int i = 0; i < 32; i += 8) {
        int n = nt + ty + i, k = kt + tx;
        g_AGt[(size_t)n * N3 + k] = __float2half(tile[tx][ty + i]);
    }
}

__global__ void kinit_scalars(const float* a0, const float* b0, const float* a1, const float* b1,
                              const float* a2, const float* b2, const float* a3, const float* b3,
                              const float* a4, const float* b4, const float* a5, const float* b5) {
    __shared__ float sm[8];
    const float* as[6] = {a0, a1, a2, a3, a4, a5};
    const float* bs[6] = {b0, b1, b2, b3, b4, b5};
    for (int p = 0; p < 6; p++) {
        float s = 0.f;
        for (int i = threadIdx.x; i < U; i += 256) s += as[p][i] * bs[p][i];
        float tot = blk_reduce_sum(s, sm);
        if (threadIdx.x == 0) g_s[p] = tot;
        __syncthreads();
    }
}

__global__ void kinit_A(const float* __restrict__ x) {
    int b = blockIdx.x;
    for (int i = threadIdx.x; i < KTOT; i += 256)
        g_A16[b * KTOT + i] = __float2half((i < Dd) ? x[(size_t)(b * T) * Dd + i] : 0.f);
    for (int i = threadIdx.x; i < U; i += 256) g_c[b * U + i] = 0.f;
}

// ---------------- fp16 mma.sync GEMM (single term) -----------------------------
// MODE 0: z (LDK=2304, KLEN=768, +bias ks0) | MODE 1: f (LDK=3072, KLEN=384)
template<int MODE>
__global__ void __launch_bounds__(256) mma_gemm(const float* __restrict__ bias) {
    constexpr int LDK  = (MODE == 0) ? KTOT : N3;
    constexpr int NTOT = (MODE == 0) ? N5 : U;
    constexpr int KLEN = (MODE == 0) ? ZKLEN : FKLEN;
    constexpr int NC   = KLEN / KCH;

    const __half* Wp = (MODE == 0) ? g_Wt : g_AGt;
    const __half* Ap = (MODE == 0) ? g_A16 : g_O16;
    float* OUT = (MODE == 0) ? g_zp : g_fp;

    const int n0    = blockIdx.x * NTILE;
    const int ks    = blockIdx.y;
    const int kbase = ks * KLEN;
    const int tid   = threadIdx.x;
    const int lane  = tid & 31;
    const int w     = tid >> 5;

    extern __shared__ char dyn[];
    const uint32_t smb = smem_u32(dyn);

    // per-thread load descriptors: 1536 segs of 16B per chunk -> 6 per thread
    const __half* srcB[6];
    uint32_t dstO[6];
    #pragma unroll
    for (int i = 0; i < 6; i++) {
        int seg = tid + i * 256;
        if (seg < 512) {
            int r = seg >> 3, s = seg & 7;
            srcB[i] = Ap + (size_t)r * LDK + s * 8;
            dstO[i] = r * ROWB + s * 16;
        } else {
            int idx = seg - 512;
            int r = idx >> 3, s = idx & 7;
            srcB[i] = Wp + (size_t)(n0 + r) * LDK + s * 8;
            dstO[i] = A_BLK + r * ROWB + s * 16;
        }
    }
    auto load_chunk = [&](int kk, int stg) {
        const uint32_t bb = smb + stg * STG_BYTES;
        #pragma unroll
        for (int i = 0; i < 6; i++)
            cpasync16(bb + dstO[i], srcB[i] + kk);
        cp_commit();
    };

    const int mrow0 = (w & 1) * 32;
    const int nrow0 = (w >> 1) * 32;
    const int rA  = mrow0 + (lane & 15);
    const int scA = lane >> 4;
    const int rB  = nrow0 + ((lane >> 4) << 3) + (lane & 7);
    const int scB = (lane >> 3) & 1;

    float acc[2][4][4] = {};

    // prologue: prefetch up to 3 chunks
    #pragma unroll
    for (int p = 0; p < 3; p++)
        if (p < NC) load_chunk(kbase + p * KCH, p);

    for (int c = 0; c < NC; c++) {
        int rem = NC - 1 - c;                  // chunks outstanding beyond c
        if (rem >= 2) cp_wait<2>(); else if (rem == 1) cp_wait<1>(); else cp_wait<0>();
        __syncthreads();
        if (c + 3 < NC) load_chunk(kbase + (c + 3) * KCH, (c + 3) % NSTG);

        const uint32_t bb = smb + (c % NSTG) * STG_BYTES;
        #pragma unroll
        for (int s16 = 0; s16 < 4; s16++) {
            const int kd = s16 * 2;
            uint32_t ah[2][4], bh[2][4];
            #pragma unroll
            for (int mi = 0; mi < 2; mi++)
                ldsm4(ah[mi], bb + (rA + mi * 16) * ROWB + (kd + scA) * 16);
            #pragma unroll
            for (int nj = 0; nj < 2; nj++)
                ldsm4(bh[nj], bb + A_BLK + (rB + nj * 16) * ROWB + (kd + scB) * 16);
            #pragma unroll
            for (int mi = 0; mi < 2; mi++)
                #pragma unroll
                for (int nf = 0; nf < 4; nf++)
                    mma16816(acc[mi][nf], ah[mi], &bh[nf >> 1][(nf & 1) * 2]);
        }
    }

    #pragma unroll
    for (int mi = 0; mi < 2; mi++) {
        #pragma unroll
        for (int nf = 0; nf < 4; nf++) {
            int row = mrow0 + mi * 16 + (lane >> 2);
            int col = n0 + nrow0 + nf * 8 + (lane & 3) * 2;
            float2 v0 = make_float2(acc[mi][nf][0], acc[mi][nf][1]);
            float2 v1 = make_float2(acc[mi][nf][2], acc[mi][nf][3]);
            if (MODE == 0 && ks == 0) {
                v0.x += bias[col]; v0.y += bias[col + 1];
                v1.x += bias[col]; v1.y += bias[col + 1];
            }
            *reinterpret_cast<float2*>(OUT + (size_t)(ks * Bsz + row) * NTOT + col) = v0;
            *reinterpret_cast<float2*>(OUT + (size_t)(ks * Bsz + row + 8) * NTOT + col) = v1;
        }
    }
}

// ---------------- gate kernel ---------------------------------------------------
__global__ void __launch_bounds__(256) kb() {
    __shared__ float sm[16];
    const int b = blockIdx.x, tid = threadIdx.x;
    const int i0 = tid * 4;

    float uz[4], dz[4], rz[4];
    {
        #define LOAD3(off, out) {                                                   \
            float4 s0 = *reinterpret_cast<const float4*>(g_zp + (size_t)(0*Bsz+b)*N5 + (off)); \
            float4 s1 = *reinterpret_cast<const float4*>(g_zp + (size_t)(1*Bsz+b)*N5 + (off)); \
            float4 s2 = *reinterpret_cast<const float4*>(g_zp + (size_t)(2*Bsz+b)*N5 + (off)); \
            out[0] = s0.x + s1.x + s2.x; out[1] = s0.y + s1.y + s2.y;                  \
            out[2] = s0.z + s1.z + s2.z; out[3] = s0.w + s1.w + s2.w; }
        LOAD3(i0,         uz)
        LOAD3(U + i0,     dz)
        LOAD3(2 * U + i0, rz)
        #undef LOAD3
    }

    float mx = fmaxf(fmaxf(uz[0], uz[1]), fmaxf(uz[2], uz[3]));
    mx = blk_reduce_max(mx, sm);
    float e[4], ls = 0.f;
    #pragma unroll
    for (int l = 0; l < 4; l++) { e[l] = expf(uz[l] - mx); ls += e[l]; }
    ScanRes s1 = blk_scan(ls, sm);
    float up[4];
    { float P = s1.excl, inv = 1.f / s1.total;
      #pragma unroll
      for (int l = 0; l < 4; l++) { P += e[l]; up[l] = P * inv; } }

    float mx2 = fmaxf(fmaxf(dz[0], dz[1]), fmaxf(dz[2], dz[3]));
    mx2 = blk_reduce_max(mx2, sm);
    float ed[4]; ls = 0.f;
    #pragma unroll
    for (int l = 0; l < 4; l++) { ed[l] = expf(dz[l] - mx2); ls += ed[l]; }
    ScanRes s2 = blk_scan(ls, sm);
    float dn[4];
    { float P = s2.excl, inv = 1.f / s2.total;
      #pragma unroll
      for (int l = 0; l < 4; l++) { P += ed[l]; dn[l] = (s2.total - P + ed[l]) * inv; } }

    float pdu = 0.f, pru = 0.f, pdr = 0.f;
    #pragma unroll
    for (int l = 0; l < 4; l++) { pdu += dn[l] * up[l]; pru += rz[l] * up[l]; pdr += dn[l] * rz[l]; }
    float du = blk_reduce_sum(pdu, sm);
    float ru = blk_reduce_sum(pru, sm);
    float dr = blk_reduce_sum(pdr, sm);

    const float s_ud = g_s[0], s_ur = g_s[1], s_ru = g_s[2];
    const float s_rd = g_s[3], s_du = g_s[4], s_dr = g_s[5];

    #pragma unroll
    for (int l = 0; l < 4; l++) {
        float t1 = sigf(s_ud * up[l] * du) + sigf(s_ur * up[l] * ru);
        float t2 = sigf(s_ru * rz[l] * ru) + sigf(s_rd * rz[l] * dr);
        float t3 = sigf(s_du * dn[l] * du) + sigf(s_dr * dn[l] * dr);
        g_O16[b * N3 + i0 + l]         = __float2half(t1);
        g_O16[b * N3 + U + i0 + l]     = __float2half(t2);
        g_O16[b * N3 + 2 * U + i0 + l] = __float2half(t3);
    }
}

// ---------------- state-update kernel -------------------------------------------
__global__ void __launch_bounds__(256) kc2(const float* __restrict__ x,
                                           float* __restrict__ out, int t) {
    const int b = blockIdx.x, tid = threadIdx.x;
    const int j0 = tid * 4;

    #pragma unroll
    for (int l = 0; l < 4; l++) {
        int j = j0 + l;
        float fs = 0.f;
        #pragma unroll
        for (int ks = 0; ks < FSPLIT; ks++) fs += g_fp[(size_t)(ks * Bsz + b) * U + j];
        float f = sigf(fs);
        float og = 0.f, zc = 0.f;
        #pragma unroll
        for (int ks = 0; ks < ZSPLIT; ks++) {
            og += g_zp[(size_t)(ks * Bsz + b) * N5 + 3 * U + j];
            zc += g_zp[(size_t)(ks * Bsz + b) * N5 + 4 * U + j];
        }
        float ci = tanhf(zc);
        float co = g_c[b * U + j];
        float cn = f * co + (1.f - f) * ci;
        float hn = og * tanhf(cn);
        g_c[b * U + j] = cn;
        out[((size_t)b * T + t) * U + j] = hn;
        g_A16[b * KTOT + Dd + j]     = __float2half(hn);
        g_A16[b * KTOT + Dd + U + j] = __float2half(cn);
    }
    if (t + 1 < T && tid < 64) {
        #pragma unroll
        for (int l = 0; l < 4; l++) {
            int d = tid * 4 + l;
            g_A16[b * KTOT + d] = __float2half(x[((size_t)b * T + (t + 1)) * Dd + d]);
        }
    }
}

// ---------------- launch ---------------------------------------------------------
extern "C" void kernel_launch(void* const* d_in, const int* in_sizes, int n_in,
                              void* d_out, int out_size) {
    const float* x    = (const float*)d_in[0];
    const float* kern = (const float*)d_in[1];
    const float* rker = (const float*)d_in[2];
    const float* cker = (const float*)d_in[3];
    const float* bias = (const float*)d_in[4];
    const float* agg  = (const float*)d_in[5];
    float* out = (float*)d_out;

    cudaFuncSetAttribute(mma_gemm<0>, cudaFuncAttributeMaxDynamicSharedMemorySize, GSMEM_BYTES);
    cudaFuncSetAttribute(mma_gemm<1>, cudaFuncAttributeMaxDynamicSharedMemorySize, GSMEM_BYTES);

    ktrans_W <<<dim3(KTOT / 32, N5 / 32), dim3(32, 8)>>>(kern, rker, cker);
    ktrans_AG<<<dim3(N3 / 32,  U  / 32), dim3(32, 8)>>>(agg);
    kinit_scalars<<<1, 256>>>((const float*)d_in[6],  (const float*)d_in[7],
                              (const float*)d_in[8],  (const float*)d_in[9],
                              (const float*)d_in[10], (const float*)d_in[11],
                              (const float*)d_in[12], (const float*)d_in[13],
                              (const float*)d_in[14], (const float*)d_in[15],
                              (const float*)d_in[16], (const float*)d_in[17]);
    kinit_A<<<Bsz, 256>>>(x);

    for (int t = 0; t < T; t++) {
        mma_gemm<0><<<dim3(N5 / NTILE, ZSPLIT), 256, GSMEM_BYTES>>>(bias);
        kb<<<Bsz, 256>>>();
        mma_gemm<1><<<dim3(U / NTILE, FSPLIT), 256, GSMEM_BYTES>>>(nullptr);
        kc2<<<Bsz, 256>>>(x, out, t);
    }
}